// round 13
// baseline (speedup 1.0000x reference)
#include <cuda_runtime.h>
#include <cuda_fp16.h>
#include <cstdint>

#define H_RES 150

// Y+X-paired fp16 planes: per scale s (W = 64<<s), entry (p,y,x) = 128B = 64 halfs:
//   [ysel 0/1][ch4 0..3] chunks of 8 halfs: { corner x ch c4*4..+3, corner x+1 ch ... }
//   ysel0 = row y, ysel1 = row min(y+1,H-1); x+1 clamped.
// scale bases (halfs): 0, 1843200, 5529600, 12902400; total 27648000 (55 MB).
__device__ __align__(16) __half g_yp[27648000];

// smem words: fp16 weights [0,16384); per-pair buf [32][68] at 16384 + pair*2176
#define OFF_BUF    16384
#define BUF_STRIDE 68
#define PAIR_WORDS 2176
#define SM_BYTES   135168

__device__ __forceinline__ uint32_t h2_of(float a, float b) {
    __half2 h = __float22half2_rn(make_float2(a, b));   // .x = low half
    return *(uint32_t*)&h;
}

__device__ __forceinline__ void mma16(float d[4], uint32_t a0, uint32_t a1,
                                      uint32_t a2, uint32_t a3,
                                      uint32_t b0, uint32_t b1) {
    asm volatile(
        "mma.sync.aligned.m16n8k16.row.col.f32.f16.f16.f32 "
        "{%0,%1,%2,%3}, {%4,%5,%6,%7}, {%8,%9}, {%0,%1,%2,%3};"
        : "+f"(d[0]), "+f"(d[1]), "+f"(d[2]), "+f"(d[3])
        : "r"(a0), "r"(a1), "r"(a2), "r"(a3), "r"(b0), "r"(b1));
}

// GEMM over 2 m16 tiles and a half-N slice (verified R8/R10/R12 code).
template<int KC, int NTT, int NTH>
__device__ __forceinline__ void gemm2m(const uint32_t* __restrict__ A,
                                       const uint2* __restrict__ Wp,
                                       int g, int q, int lane, float acc[2][NTH][4]) {
#pragma unroll
    for (int mt = 0; mt < 2; mt++)
#pragma unroll
        for (int n8 = 0; n8 < NTH; n8++)
#pragma unroll
            for (int i = 0; i < 4; i++) acc[mt][n8][i] = 0.f;

    const uint32_t* r0lo = A + g * BUF_STRIDE;
    const uint32_t* r0hi = A + (g + 8) * BUF_STRIDE;
    const uint32_t* r1lo = A + (g + 16) * BUF_STRIDE;
    const uint32_t* r1hi = A + (g + 24) * BUF_STRIDE;

#pragma unroll
    for (int k16 = 0; k16 < KC; k16++) {
        int cw = k16 * 8 + q;
        uint32_t a00 = r0lo[cw], a01 = r0hi[cw], a02 = r0lo[cw + 4], a03 = r0hi[cw + 4];
        uint32_t a10 = r1lo[cw], a11 = r1hi[cw], a12 = r1lo[cw + 4], a13 = r1hi[cw + 4];
        const uint2* W2 = Wp + (size_t)(k16 * NTT) * 32 + lane;
#pragma unroll
        for (int n8 = 0; n8 < NTH; n8++) {
            uint2 b = W2[n8 * 32];
            mma16(acc[0][n8], a00, a01, a02, a03, b.x, b.y);
            mma16(acc[1][n8], a10, a11, a12, a13, b.x, b.y);
        }
    }
}

// ---- prologue: build y+x-paired fp16 planes from [3,16,150,W] fp32 sources ----
// Domain i = x-paired half index (13.8M); each value lands in 2-3 y-paired slots.
__global__ void prep_kernel(const float* __restrict__ p0, const float* __restrict__ p1,
                            const float* __restrict__ p2, const float* __restrict__ p3) {
    const int total = 13824000;
    for (int i = blockIdx.x * blockDim.x + threadIdx.x; i < total;
         i += gridDim.x * blockDim.x) {
        int s, base, ybase;
        const float* src;
        if (i < 921600)       { s = 0; base = 0;       ybase = 0;        src = p0; }
        else if (i < 2764800) { s = 1; base = 921600;  ybase = 1843200;  src = p1; }
        else if (i < 6451200) { s = 2; base = 2764800; ybase = 5529600;  src = p2; }
        else                  { s = 3; base = 6451200; ybase = 12902400; src = p3; }
        int W = 64 << s;
        int li = i - base;
        int within = li & 31;          // chunk offset within 64B half-entry
        int ent = li >> 5;
        int c4  = within >> 3;
        int xs  = (within >> 2) & 1;
        int chl = within & 3;
        int ch  = c4 * 4 + chl;
        int x = ent % W; ent /= W;
        int y = ent % H_RES;
        int p = ent / H_RES;
        int xcol = min(x + xs, W - 1);
        __half v = __float2half(src[((p * 16 + ch) * H_RES + y) * W + xcol]);

        // entry(y).ysel0 gets row y
        g_yp[ybase + (size_t)((p * H_RES + y) * W + x) * 64 + within] = v;
        // entry(y-1).ysel1 gets row y
        if (y > 0)
            g_yp[ybase + (size_t)((p * H_RES + (y - 1)) * W + x) * 64 + 32 + within] = v;
        // clamp: entry(H-1).ysel1 gets row H-1
        if (y == H_RES - 1)
            g_yp[ybase + (size_t)((p * H_RES + y) * W + x) * 64 + 32 + within] = v;
    }
}

// ---- persistent fused kernel: 8 warp-pairs, pair owns 32 pts, N split across pair ----
__global__ void __launch_bounds__(512, 1) fused_kernel(
    const float4* __restrict__ pts,
    const float*  __restrict__ w0, const float* __restrict__ b0,
    const float*  __restrict__ w1, const float* __restrict__ b1,
    const float*  __restrict__ w2, const float* __restrict__ b2,
    float*        __restrict__ out, int n, int ntiles)
{
    extern __shared__ uint32_t sm[];
    const int tid  = threadIdx.x;
    const int lane = tid & 31;
    const int g    = lane >> 2;
    const int q    = lane & 3;
    const int wrp  = tid >> 5;
    const int pair = wrp >> 1;
    const int half = wrp & 1;
    const int bar  = pair + 1;

    // ---- stage fp16 weights once, fragment-packed uint2 ----
    for (int e = tid; e < 8192; e += 512) {
        const float* W; int K, nt, le;
        if (e < 2048)      { W = w0; K = 64;  nt = 16; le = e; }
        else if (e < 6144) { W = w1; K = 128; nt = 16; le = e - 2048; }
        else               { W = w2; K = 128; nt = 8;  le = e - 6144; }
        int perk = nt * 32;
        int k16 = le / perk;
        int r   = le % perk;
        int n8  = r >> 5;
        int ln  = r & 31;
        int nrow = n8 * 8 + (ln >> 2);
        int kb   = k16 * 16 + 2 * (ln & 3);
        const float* src = W + nrow * K + kb;
        uint2 v = { h2_of(src[0], src[1]), h2_of(src[8], src[9]) };
        ((uint2*)sm)[e] = v;
    }
    __syncthreads();

    uint32_t* buf = sm + OFF_BUF + pair * PAIR_WORDS;   // per-pair [32][68]
    const uint2* Wp0 = (const uint2*)sm         + half * 8 * 32;
    const uint2* Wp1 = (const uint2*)sm + 2048  + half * 8 * 32;
    const uint2* Wp2 = (const uint2*)sm + 6144  + half * 4 * 32;

    const int scale_off[4] = {0, 1843200, 5529600, 12902400};

    const int ch4  = lane & 3;          // channel chunk (4 channels)
    const int ysel = (lane >> 2) & 1;   // y corner handled by this lane
    const int pidx = lane >> 3;         // point index within pass (0..3)

#define PBAR() asm volatile("bar.sync %0, 64;" :: "r"(bar) : "memory")

    for (int t = blockIdx.x; t < ntiles; t += gridDim.x) {
        const int rowb = t * 256 + pair * 32;

        // ---- 1. sampling: 8 lanes/point; 128B y+x-paired entries (1 line/point) ----
#pragma unroll
        for (int pass = 0; pass < 4; pass++) {
            const int pr = half * 16 + pass * 4 + pidx;
            int ptc = min(rowb + pr, n - 1);
            float4 P = pts[ptc];

            float fy = (P.w + 1.0f) * 0.5f * (float)(H_RES - 1);
            fy = fminf(fmaxf(fy, 0.0f), (float)(H_RES - 1));
            int   iy0 = (int)floorf(fy);
            float wyv = fy - (float)iy0;
            float wyl = ysel ? wyv : (1.0f - wyv);
            float coord[3] = {P.x, P.y, P.z};

#pragma unroll
            for (int s = 0; s < 4; s++) {
                const int W = 64 << s;
                float prod[4] = {1.f, 1.f, 1.f, 1.f};
#pragma unroll
                for (int p = 0; p < 3; p++) {
                    float x  = coord[p];
                    float fx = (x + 1.0f) * 0.5f * (float)(W - 1);
                    fx = fminf(fmaxf(fx, 0.0f), (float)(W - 1));
                    int   ix0 = (int)floorf(fx);
                    float wx  = fx - (float)ix0;

                    const __half* pb = g_yp + scale_off[s]
                                       + (size_t)p * (H_RES * W * 64);
                    uint4 E = *(const uint4*)(pb + (size_t)(iy0 * W + ix0) * 64
                                              + ysel * 32 + ch4 * 8);

                    float w0x = 1.0f - wx;
                    float2 x0a = __half22float2(*(const __half2*)&E.x);  // x0 ch0,1
                    float2 x0b = __half22float2(*(const __half2*)&E.y);  // x0 ch2,3
                    float2 x1a = __half22float2(*(const __half2*)&E.z);  // x1 ch0,1
                    float2 x1b = __half22float2(*(const __half2*)&E.w);  // x1 ch2,3

                    float p0v = (x0a.x * w0x + x1a.x * wx) * wyl;
                    float p1v = (x0a.y * w0x + x1a.y * wx) * wyl;
                    float p2v = (x0b.x * w0x + x1b.x * wx) * wyl;
                    float p3v = (x0b.y * w0x + x1b.y * wx) * wyl;

                    // y-reduction across ysel partner lane (lane ^ 4)
                    p0v += __shfl_xor_sync(0xFFFFFFFFu, p0v, 4);
                    p1v += __shfl_xor_sync(0xFFFFFFFFu, p1v, 4);
                    p2v += __shfl_xor_sync(0xFFFFFFFFu, p2v, 4);
                    p3v += __shfl_xor_sync(0xFFFFFFFFu, p3v, 4);

                    prod[0] *= p0v;
                    prod[1] *= p1v;
                    prod[2] *= p2v;
                    prod[3] *= p3v;
                }
                if (ysel == 0) {
                    uint2 v = { h2_of(prod[0], prod[1]), h2_of(prod[2], prod[3]) };
                    *(uint2*)(buf + pr * BUF_STRIDE + s * 8 + ch4 * 2) = v;
                }
            }
        }
        PBAR();

        // ---- 2. layer0: acc = F[32x64] @ w0^T (half-N) ----
        float acc[2][8][4];
        gemm2m<4, 16, 8>(buf, Wp0, g, q, lane, acc);
        PBAR();

        // ---- 3. epilogue0: H(half cols) = fp16(relu(acc + b0)) ----
#pragma unroll
        for (int n8 = 0; n8 < 8; n8++) {
            int col = (half * 8 + n8) * 8 + 2 * q;
            int w   = (half * 8 + n8) * 4 + q;
            float bb0 = __ldg(b0 + col), bb1 = __ldg(b0 + col + 1);
#pragma unroll
            for (int mt = 0; mt < 2; mt++) {
                buf[(mt * 16 + g) * BUF_STRIDE + w] =
                    h2_of(fmaxf(acc[mt][n8][0] + bb0, 0.f), fmaxf(acc[mt][n8][1] + bb1, 0.f));
                buf[(mt * 16 + g + 8) * BUF_STRIDE + w] =
                    h2_of(fmaxf(acc[mt][n8][2] + bb0, 0.f), fmaxf(acc[mt][n8][3] + bb1, 0.f));
            }
        }
        PBAR();

        // ---- 4. layer1: acc = H[32x128] @ w1^T (half-N) ----
        gemm2m<8, 16, 8>(buf, Wp1, g, q, lane, acc);
        PBAR();

        // ---- 5. epilogue1: H(half cols) = fp16(relu(acc + b1)) ----
#pragma unroll
        for (int n8 = 0; n8 < 8; n8++) {
            int col = (half * 8 + n8) * 8 + 2 * q;
            int w   = (half * 8 + n8) * 4 + q;
            float bb0 = __ldg(b1 + col), bb1 = __ldg(b1 + col + 1);
#pragma unroll
            for (int mt = 0; mt < 2; mt++) {
                buf[(mt * 16 + g) * BUF_STRIDE + w] =
                    h2_of(fmaxf(acc[mt][n8][0] + bb0, 0.f), fmaxf(acc[mt][n8][1] + bb1, 0.f));
                buf[(mt * 16 + g + 8) * BUF_STRIDE + w] =
                    h2_of(fmaxf(acc[mt][n8][2] + bb0, 0.f), fmaxf(acc[mt][n8][3] + bb1, 0.f));
            }
        }
        PBAR();

        // ---- 6. layer2: acc3 = H @ w2^T (half of N=64) + output ----
        float acc3[2][4][4];
        gemm2m<8, 8, 4>(buf, Wp2, g, q, lane, acc3);

#pragma unroll
        for (int n8 = 0; n8 < 4; n8++) {
            int col = (half * 4 + n8) * 8 + 2 * q;
            float bb0 = __ldg(b2 + col), bb1 = __ldg(b2 + col + 1);
#pragma unroll
            for (int mt = 0; mt < 2; mt++) {
                int r0 = rowb + mt * 16 + g;
                if (r0 < n) {
                    float2 o = { acc3[mt][n8][0] + bb0, acc3[mt][n8][1] + bb1 };
                    *(float2*)(out + (size_t)r0 * 64 + col) = o;
                }
                if (r0 + 8 < n) {
                    float2 o = { acc3[mt][n8][2] + bb0, acc3[mt][n8][3] + bb1 };
                    *(float2*)(out + (size_t)(r0 + 8) * 64 + col) = o;
                }
            }
        }
        PBAR();   // buf (H) fully consumed before next tile's sampling overwrites
    }
#undef PBAR
}

extern "C" void kernel_launch(void* const* d_in, const int* in_sizes, int n_in,
                              void* d_out, int out_size) {
    const float* pts = (const float*)d_in[0];
    const float* p0  = (const float*)d_in[1];
    const float* p1  = (const float*)d_in[2];
    const float* p2  = (const float*)d_in[3];
    const float* p3  = (const float*)d_in[4];
    const float* w0  = (const float*)d_in[5];
    const float* b0  = (const float*)d_in[6];
    const float* w1  = (const float*)d_in[7];
    const float* b1  = (const float*)d_in[8];
    const float* w2  = (const float*)d_in[9];
    const float* b2  = (const float*)d_in[10];

    int n = in_sizes[0] / 4;
    int ntiles = (n + 255) / 256;

    int sm_count = 148;
    cudaDeviceGetAttribute(&sm_count, cudaDevAttrMultiProcessorCount, 0);

    cudaFuncSetAttribute(fused_kernel, cudaFuncAttributeMaxDynamicSharedMemorySize, SM_BYTES);

    prep_kernel<<<13500, 512>>>(p0, p1, p2, p3);
    fused_kernel<<<sm_count, 512, SM_BYTES>>>(
        (const float4*)pts, w0, b0, w1, b1, w2, b2, (float*)d_out, n, ntiles);
}

// round 16
// speedup vs baseline: 1.1772x; 1.1772x over previous
#include <cuda_runtime.h>
#include <cuda_fp16.h>
#include <cstdint>

#define H_RES 150

// X-paired fp16 planes: per scale s (W = 64<<s), entry (p,y,x) = 32 halfs:
// 4 chunks of 8 halfs: chunk c4 = { corner x ch c4*4..+3, corner x+1 ch c4*4..+3 }
// scale bases (halfs): 0, 921600, 2764800, 6451200; total 13824000.
__device__ __align__(16) __half g_pp[13824000];

// smem words: fp16 weights [0,16384); per-pair buf [32][68] at 16384 + pair*2176
#define OFF_BUF    16384
#define BUF_STRIDE 68
#define PAIR_WORDS 2176
#define SM_BYTES   135168

__device__ __forceinline__ uint32_t h2_of(float a, float b) {
    __half2 h = __float22half2_rn(make_float2(a, b));   // .x = low half
    return *(uint32_t*)&h;
}

__device__ __forceinline__ void mma16(float d[4], uint32_t a0, uint32_t a1,
                                      uint32_t a2, uint32_t a3,
                                      uint32_t b0, uint32_t b1) {
    asm volatile(
        "mma.sync.aligned.m16n8k16.row.col.f32.f16.f16.f32 "
        "{%0,%1,%2,%3}, {%4,%5,%6,%7}, {%8,%9}, {%0,%1,%2,%3};"
        : "+f"(d[0]), "+f"(d[1]), "+f"(d[2]), "+f"(d[3])
        : "r"(a0), "r"(a1), "r"(a2), "r"(a3), "r"(b0), "r"(b1));
}

// GEMM over 2 m16 tiles and a half-N slice; weights k16-PAIR packed as uint4:
// entry ((k16p*NTT + n8)*32 + lane) = { k16even.b0,b1, k16odd.b0,b1 }.
template<int KC, int NTT, int NTH>
__device__ __forceinline__ void gemm2m(const uint32_t* __restrict__ A,
                                       const uint4* __restrict__ Wp,
                                       int g, int q, int lane, float acc[2][NTH][4]) {
#pragma unroll
    for (int mt = 0; mt < 2; mt++)
#pragma unroll
        for (int n8 = 0; n8 < NTH; n8++)
#pragma unroll
            for (int i = 0; i < 4; i++) acc[mt][n8][i] = 0.f;

    const uint32_t* r0lo = A + g * BUF_STRIDE;
    const uint32_t* r0hi = A + (g + 8) * BUF_STRIDE;
    const uint32_t* r1lo = A + (g + 16) * BUF_STRIDE;
    const uint32_t* r1hi = A + (g + 24) * BUF_STRIDE;

#pragma unroll
    for (int k16p = 0; k16p < KC / 2; k16p++) {
        int cw = k16p * 16 + q;
        // a-frags for k16 even (cw..cw+4) and k16 odd (cw+8..cw+12), both m-tiles
        uint32_t a00 = r0lo[cw],      a01 = r0hi[cw];
        uint32_t a02 = r0lo[cw + 4],  a03 = r0hi[cw + 4];
        uint32_t a04 = r0lo[cw + 8],  a05 = r0hi[cw + 8];
        uint32_t a06 = r0lo[cw + 12], a07 = r0hi[cw + 12];
        uint32_t a10 = r1lo[cw],      a11 = r1hi[cw];
        uint32_t a12 = r1lo[cw + 4],  a13 = r1hi[cw + 4];
        uint32_t a14 = r1lo[cw + 8],  a15 = r1hi[cw + 8];
        uint32_t a16 = r1lo[cw + 12], a17 = r1hi[cw + 12];
        const uint4* W4 = Wp + (size_t)(k16p * NTT) * 32 + lane;
#pragma unroll
        for (int n8 = 0; n8 < NTH; n8++) {
            uint4 b = W4[n8 * 32];
            mma16(acc[0][n8], a00, a01, a02, a03, b.x, b.y);
            mma16(acc[0][n8], a04, a05, a06, a07, b.z, b.w);
            mma16(acc[1][n8], a10, a11, a12, a13, b.x, b.y);
            mma16(acc[1][n8], a14, a15, a16, a17, b.z, b.w);
        }
    }
}

// ---- prologue: build x-paired fp16 planes from [3,16,150,W] fp32 sources ----
__global__ void prep_kernel(const float* __restrict__ p0, const float* __restrict__ p1,
                            const float* __restrict__ p2, const float* __restrict__ p3) {
    const int total = 13824000;
    for (int i = blockIdx.x * blockDim.x + threadIdx.x; i < total;
         i += gridDim.x * blockDim.x) {
        int s, base;
        const float* src;
        if (i < 921600)       { s = 0; base = 0;       src = p0; }
        else if (i < 2764800) { s = 1; base = 921600;  src = p1; }
        else if (i < 6451200) { s = 2; base = 2764800; src = p2; }
        else                  { s = 3; base = 6451200; src = p3; }
        int W = 64 << s;
        int li = i - base;
        int within = li & 31;          // half index within 64B entry
        int ent = li >> 5;
        int c4  = within >> 3;         // channel chunk
        int xs  = (within >> 2) & 1;   // x-corner select
        int chl = within & 3;
        int ch  = c4 * 4 + chl;
        int x = ent % W; ent /= W;
        int y = ent % H_RES;
        int p = ent / H_RES;
        int xcol = min(x + xs, W - 1);
        g_pp[i] = __float2half(src[((p * 16 + ch) * H_RES + y) * W + xcol]);
    }
}

// ---- persistent fused kernel: 8 warp-pairs, pair owns 32 pts, N split across pair ----
__global__ void __launch_bounds__(512, 1) fused_kernel(
    const float4* __restrict__ pts,
    const float*  __restrict__ w0, const float* __restrict__ b0,
    const float*  __restrict__ w1, const float* __restrict__ b1,
    const float*  __restrict__ w2, const float* __restrict__ b2,
    float*        __restrict__ out, int n, int ntiles)
{
    extern __shared__ uint32_t sm[];
    const int tid  = threadIdx.x;
    const int lane = tid & 31;
    const int g    = lane >> 2;
    const int q    = lane & 3;
    const int wrp  = tid >> 5;
    const int pair = wrp >> 1;
    const int half = wrp & 1;
    const int bar  = pair + 1;

    // ---- stage fp16 weights once, k16-pair packed uint4 ----
    // uint4 entry layout per layer: L0 [0,1024), L1 [1024,3072), L2 [3072,4096)
    for (int e = tid; e < 4096; e += 512) {
        const float* W; int K, nt, le;
        if (e < 1024)      { W = w0; K = 64;  nt = 16; le = e; }
        else if (e < 3072) { W = w1; K = 128; nt = 16; le = e - 1024; }
        else               { W = w2; K = 128; nt = 8;  le = e - 3072; }
        int perk = nt * 32;
        int k16p = le / perk;
        int r    = le % perk;
        int n8   = r >> 5;
        int ln   = r & 31;
        int nrow = n8 * 8 + (ln >> 2);
        int kb   = k16p * 32 + 2 * (ln & 3);
        const float* src = W + nrow * K + kb;
        uint4 v = { h2_of(src[0],  src[1]),  h2_of(src[8],  src[9]),
                    h2_of(src[16], src[17]), h2_of(src[24], src[25]) };
        ((uint4*)sm)[e] = v;
    }
    __syncthreads();

    uint32_t* buf = sm + OFF_BUF + pair * PAIR_WORDS;   // per-pair [32][68]
    const uint4* Wp0 = (const uint4*)sm         + half * 8 * 32;
    const uint4* Wp1 = (const uint4*)sm + 1024  + half * 8 * 32;
    const uint4* Wp2 = (const uint4*)sm + 3072  + half * 4 * 32;

    const int scale_off[4] = {0, 921600, 2764800, 6451200};

    const int ch4  = lane & 3;    // channel chunk (4 channels)
    const int pidx = lane >> 2;   // point index within pass (0..7)

#define PBAR() asm volatile("bar.sync %0, 64;" :: "r"(bar) : "memory")

    for (int t = blockIdx.x; t < ntiles; t += gridDim.x) {
        const int rowb = t * 256 + pair * 32;

        // ---- 1. sampling: 4 lanes/point; x-paired entries, 2 loads per (s,p) ----
#pragma unroll
        for (int pass = 0; pass < 2; pass++) {
            const int pr = half * 16 + pass * 8 + pidx;
            int ptc = min(rowb + pr, n - 1);
            float4 P = pts[ptc];

            float fy = (P.w + 1.0f) * 0.5f * (float)(H_RES - 1);
            fy = fminf(fmaxf(fy, 0.0f), (float)(H_RES - 1));
            int   iy0 = (int)floorf(fy);
            int   iy1 = min(iy0 + 1, H_RES - 1);
            float wyv = fy - (float)iy0;
            float coord[3] = {P.x, P.y, P.z};

#pragma unroll
            for (int s = 0; s < 4; s++) {
                const int W = 64 << s;
                float prod[4] = {1.f, 1.f, 1.f, 1.f};
#pragma unroll
                for (int p = 0; p < 3; p++) {
                    float x  = coord[p];
                    float fx = (x + 1.0f) * 0.5f * (float)(W - 1);
                    fx = fminf(fmaxf(fx, 0.0f), (float)(W - 1));
                    int   ix0 = (int)floorf(fx);
                    float wx  = fx - (float)ix0;

                    const __half* pb = g_pp + scale_off[s] + p * (H_RES * W * 32);
                    uint4 E0 = *(const uint4*)(pb + (iy0 * W + ix0) * 32 + ch4 * 8);
                    uint4 E1 = *(const uint4*)(pb + (iy1 * W + ix0) * 32 + ch4 * 8);

                    float w00 = (1.0f - wx) * (1.0f - wyv);
                    float w01 = wx * (1.0f - wyv);
                    float w10 = (1.0f - wx) * wyv;
                    float w11 = wx * wyv;

                    float2 a01 = __half22float2(*(const __half2*)&E0.x);  // x0 ch0,1
                    float2 a23 = __half22float2(*(const __half2*)&E0.y);  // x0 ch2,3
                    float2 b01 = __half22float2(*(const __half2*)&E0.z);  // x1 ch0,1
                    float2 b23 = __half22float2(*(const __half2*)&E0.w);  // x1 ch2,3
                    float2 c01 = __half22float2(*(const __half2*)&E1.x);
                    float2 c23 = __half22float2(*(const __half2*)&E1.y);
                    float2 d01 = __half22float2(*(const __half2*)&E1.z);
                    float2 d23 = __half22float2(*(const __half2*)&E1.w);

                    prod[0] *= a01.x*w00 + b01.x*w01 + c01.x*w10 + d01.x*w11;
                    prod[1] *= a01.y*w00 + b01.y*w01 + c01.y*w10 + d01.y*w11;
                    prod[2] *= a23.x*w00 + b23.x*w01 + c23.x*w10 + d23.x*w11;
                    prod[3] *= a23.y*w00 + b23.y*w01 + c23.y*w10 + d23.y*w11;
                }
                uint2 v = { h2_of(prod[0], prod[1]), h2_of(prod[2], prod[3]) };
                *(uint2*)(buf + pr * BUF_STRIDE + s * 8 + ch4 * 2) = v;
            }
        }
        PBAR();

        // ---- 2. layer0: acc = F[32x64] @ w0^T (half-N) ----
        float acc[2][8][4];
        gemm2m<4, 16, 8>(buf, Wp0, g, q, lane, acc);
        PBAR();

        // ---- 3. epilogue0: H(half cols) = fp16(relu(acc + b0)) ----
#pragma unroll
        for (int n8 = 0; n8 < 8; n8++) {
            int col = (half * 8 + n8) * 8 + 2 * q;
            int w   = (half * 8 + n8) * 4 + q;
            float bb0 = __ldg(b0 + col), bb1 = __ldg(b0 + col + 1);
#pragma unroll
            for (int mt = 0; mt < 2; mt++) {
                buf[(mt * 16 + g) * BUF_STRIDE + w] =
                    h2_of(fmaxf(acc[mt][n8][0] + bb0, 0.f), fmaxf(acc[mt][n8][1] + bb1, 0.f));
                buf[(mt * 16 + g + 8) * BUF_STRIDE + w] =
                    h2_of(fmaxf(acc[mt][n8][2] + bb0, 0.f), fmaxf(acc[mt][n8][3] + bb1, 0.f));
            }
        }
        PBAR();

        // ---- 4. layer1: acc = H[32x128] @ w1^T (half-N) ----
        gemm2m<8, 16, 8>(buf, Wp1, g, q, lane, acc);
        PBAR();

        // ---- 5. epilogue1: H(half cols) = fp16(relu(acc + b1)) ----
#pragma unroll
        for (int n8 = 0; n8 < 8; n8++) {
            int col = (half * 8 + n8) * 8 + 2 * q;
            int w   = (half * 8 + n8) * 4 + q;
            float bb0 = __ldg(b1 + col), bb1 = __ldg(b1 + col + 1);
#pragma unroll
            for (int mt = 0; mt < 2; mt++) {
                buf[(mt * 16 + g) * BUF_STRIDE + w] =
                    h2_of(fmaxf(acc[mt][n8][0] + bb0, 0.f), fmaxf(acc[mt][n8][1] + bb1, 0.f));
                buf[(mt * 16 + g + 8) * BUF_STRIDE + w] =
                    h2_of(fmaxf(acc[mt][n8][2] + bb0, 0.f), fmaxf(acc[mt][n8][3] + bb1, 0.f));
            }
        }
        PBAR();

        // ---- 6. layer2: acc3 = H @ w2^T (half of N=64) + output ----
        float acc3[2][4][4];
        gemm2m<8, 8, 4>(buf, Wp2, g, q, lane, acc3);

#pragma unroll
        for (int n8 = 0; n8 < 4; n8++) {
            int col = (half * 4 + n8) * 8 + 2 * q;
            float bb0 = __ldg(b2 + col), bb1 = __ldg(b2 + col + 1);
#pragma unroll
            for (int mt = 0; mt < 2; mt++) {
                int r0 = rowb + mt * 16 + g;
                if (r0 < n) {
                    float2 o = { acc3[mt][n8][0] + bb0, acc3[mt][n8][1] + bb1 };
                    *(float2*)(out + (size_t)r0 * 64 + col) = o;
                }
                if (r0 + 8 < n) {
                    float2 o = { acc3[mt][n8][2] + bb0, acc3[mt][n8][3] + bb1 };
                    *(float2*)(out + (size_t)(r0 + 8) * 64 + col) = o;
                }
            }
        }
        PBAR();   // buf (H) fully consumed before next tile's sampling overwrites
    }
#undef PBAR
}

extern "C" void kernel_launch(void* const* d_in, const int* in_sizes, int n_in,
                              void* d_out, int out_size) {
    const float* pts = (const float*)d_in[0];
    const float* p0  = (const float*)d_in[1];
    const float* p1  = (const float*)d_in[2];
    const float* p2  = (const float*)d_in[3];
    const float* p3  = (const float*)d_in[4];
    const float* w0  = (const float*)d_in[5];
    const float* b0  = (const float*)d_in[6];
    const float* w1  = (const float*)d_in[7];
    const float* b1  = (const float*)d_in[8];
    const float* w2  = (const float*)d_in[9];
    const float* b2  = (const float*)d_in[10];

    int n = in_sizes[0] / 4;
    int ntiles = (n + 255) / 256;

    int sm_count = 148;
    cudaDeviceGetAttribute(&sm_count, cudaDevAttrMultiProcessorCount, 0);

    cudaFuncSetAttribute(fused_kernel, cudaFuncAttributeMaxDynamicSharedMemorySize, SM_BYTES);

    prep_kernel<<<13500, 512>>>(p0, p1, p2, p3);
    fused_kernel<<<sm_count, 512, SM_BYTES>>>(
        (const float4*)pts, w0, b0, w1, b1, w2, b2, (float*)d_out, n, ntiles);
}